// round 13
// baseline (speedup 1.0000x reference)
#include <cuda_runtime.h>
#include <cuda_fp16.h>
#include <math.h>
#include <cstdint>

#define NN 65535            // total nodes
#define LEAF_START 32767
#define NMEM 256

// ---- scratch (device globals; no allocation allowed) ----
__device__ float  g_PRE[(size_t)NN * 1024];      // [N,1024]: 0..767 x@W_ioux^T, 768..1023 x@W_fx^T
__device__ float  g_PIOU[(size_t)16384 * 768];   // per-level iou recurrent term [S,768]
__device__ float  g_PF[(size_t)32768 * 256];     // per-level child f-projections [2S,256]
__device__ __half g_X16[(size_t)NN * 320];       // inputs fp16, K padded 300->320
__device__ __half g_W1h[1024 * 320];             // gemm1 B fp16 [n][k]
__device__ __half g_WIOUh[768 * 256];            // W_iouh fp16 [n][k]
__device__ __half g_WFh[256 * 256];              // W_fh fp16 [n][k]
__device__ __half g_H16[(size_t)NN * 256];       // h in fp16
__device__ float  g_BIO[768];                    // b_ioux + b_iouh
__device__ float  g_BF[256];                     // b_fx + b_fh

// ============================ helpers ============================
__device__ __forceinline__ uint32_t smem_u32(const void* p) {
    uint32_t a;
    asm("{ .reg .u64 t; cvta.to.shared.u64 t, %1; cvt.u32.u64 %0, t; }" : "=r"(a) : "l"(p));
    return a;
}
__device__ __forceinline__ uint32_t hadd2u(uint32_t a, uint32_t b) {
    __half2 r = __hadd2(*reinterpret_cast<__half2*>(&a), *reinterpret_cast<__half2*>(&b));
    return *reinterpret_cast<uint32_t*>(&r);
}

// ============================ conversion / repacking ============================
__global__ void conv_x(const float* __restrict__ inputs) {
    int idx = blockIdx.x * blockDim.x + threadIdx.x;     // over 65535*160 half2
    if (idx >= NN * 160) return;
    int row = idx / 160, c2 = idx - row * 160;
    int k = 2 * c2;
    __half2 v;
    if (k < 300) {
        float2 f = *(const float2*)&inputs[(size_t)row * 300 + k];
        v = __floats2half2_rn(f.x, f.y);
    } else {
        v = __floats2half2_rn(0.f, 0.f);
    }
    *(__half2*)&g_X16[(size_t)row * 320 + k] = v;
}

__global__ void build_w1h(const float* __restrict__ W_ioux, const float* __restrict__ W_fx) {
    int idx = blockIdx.x * blockDim.x + threadIdx.x;
    if (idx >= 1024 * 320) return;
    int j = idx / 320, k = idx - j * 320;
    float v = 0.f;
    if (k < 300) v = (j < 768) ? W_ioux[j * 300 + k] : W_fx[(j - 768) * 300 + k];
    g_W1h[idx] = __float2half_rn(v);
}

__global__ void build_misch(const float* __restrict__ W_iouh, const float* __restrict__ W_fh,
                            const float* __restrict__ b_ioux, const float* __restrict__ b_iouh,
                            const float* __restrict__ b_fx, const float* __restrict__ b_fh) {
    int i = blockIdx.x * blockDim.x + threadIdx.x;
    if (i < 196608)       g_WIOUh[i] = __float2half_rn(W_iouh[i]);
    else if (i < 262144)  g_WFh[i - 196608] = __float2half_rn(W_fh[i - 196608]);
    else if (i < 262912)  { int j = i - 262144; g_BIO[j] = b_ioux[j] + b_iouh[j]; }
    else if (i < 263168)  { int j = i - 262912; g_BF[j]  = b_fx[j]  + b_fh[j];  }
}

// ============================ smem tiling constants (fp16) ============================
#define SROW_H 40                       // 32 + 8 pad halves per smem row (80 B, conflict-free)
#define TILE_H (128 * SROW_H)           // one 128x32-half tile
#define STAGE_H (2 * TILE_H)            // A + B per stage (level gemm)
#define TILE_B256 (256 * SROW_H)        // 256x32-half B tile (gemm1)
#define STAGE256 (TILE_H + TILE_B256)   // gemm1 stage: A(128) + B(256)

// fp16 mma: D += A(16x16) * B^T(8x16)
#define HMMA(accp, a0, a1, a2, a3, b0, b1)                                         \
    asm volatile(                                                                  \
        "mma.sync.aligned.m16n8k16.row.col.f32.f16.f16.f32 "                       \
        "{%0,%1,%2,%3}, {%4,%5,%6,%7}, {%8,%9}, {%0,%1,%2,%3};"                    \
        : "+f"((accp)[0]), "+f"((accp)[1]), "+f"((accp)[2]), "+f"((accp)[3])       \
        : "r"(a0), "r"(a1), "r"(a2), "r"(a3), "r"(b0), "r"(b1))

// ============================ gemm1: X16[M,320] @ W1h[.,320]^T -> PRE fp32 ============================
// CTA tile 128x256, 8 warps (2x4), 64x64 warp tiles, 3-stage cp.async, scalar fragment loads.
__device__ __forceinline__ void g1_load(__half* dst, const __half* __restrict__ X,
                                        const __half* __restrict__ W,
                                        int M, int bm, int ncol, int k0, int tid) {
    // A: threads 0..127 load one 64B row each
    if (tid < 128) {
        const int row = tid;
        const bool ok = (bm + row) < M;
        const __half* ga = ok ? (X + (size_t)(bm + row) * 320 + k0) : X;
        uint32_t sa = smem_u32(dst + row * SROW_H);
        uint32_t sz = ok ? 16u : 0u;
#pragma unroll
        for (int i = 0; i < 4; i++)
            asm volatile("cp.async.cg.shared.global [%0], [%1], 16, %2;"
                         :: "r"(sa + 16u * i), "l"(ga + 8 * i), "r"(sz) : "memory");
    }
    // B: all 256 threads load one 64B row each (256 rows)
    {
        const int row = tid;
        const __half* gb = W + (size_t)(ncol + row) * 320 + k0;
        uint32_t sb = smem_u32(dst + TILE_H + row * SROW_H);
#pragma unroll
        for (int i = 0; i < 4; i++)
            asm volatile("cp.async.cg.shared.global [%0], [%1], 16;"
                         :: "r"(sb + 16u * i), "l"(gb + 8 * i) : "memory");
    }
}

__global__ __launch_bounds__(256)
void gemm1_h(const __half* __restrict__ X, const __half* __restrict__ W,
             float* __restrict__ C, int M, int bn0) {
    extern __shared__ __half smh[];
    const int tid  = threadIdx.x;
    const int wid  = tid >> 5;
    const int lane = tid & 31;
    const int wm = wid & 1, wn = wid >> 1;     // 2x4 warp grid: 64-row x 64-col warp tiles
    const int g  = lane >> 2, c4 = lane & 3;
    const int bm = blockIdx.y * 128;
    const int ncol = bn0 + blockIdx.x * 256;
    const int KC = 10;

    float acc[4][8][4];
#pragma unroll
    for (int mt = 0; mt < 4; mt++)
#pragma unroll
        for (int nt = 0; nt < 8; nt++)
#pragma unroll
            for (int i = 0; i < 4; i++) acc[mt][nt][i] = 0.f;

    g1_load(smh, X, W, M, bm, ncol, 0, tid);
    asm volatile("cp.async.commit_group;" ::: "memory");
    g1_load(smh + STAGE256, X, W, M, bm, ncol, 32, tid);
    asm volatile("cp.async.commit_group;" ::: "memory");
    asm volatile("cp.async.wait_group 1;" ::: "memory");
    __syncthreads();

    int st = 0;
    for (int ci = 0; ci < KC; ci++) {
        const __half* As = smh + (size_t)st * STAGE256;
        const __half* Bs = As + TILE_H;
#pragma unroll
        for (int ks = 0; ks < 2; ks++) {
            const int kb = ks * 16;
            uint32_t a[4][4];
#pragma unroll
            for (int mt = 0; mt < 4; mt++) {
                const __half* ap = As + (wm * 64 + mt * 16 + g) * SROW_H + kb + 2 * c4;
                a[mt][0] = *(const uint32_t*)ap;
                a[mt][1] = *(const uint32_t*)(ap + 8 * SROW_H);
                a[mt][2] = *(const uint32_t*)(ap + 8);
                a[mt][3] = *(const uint32_t*)(ap + 8 * SROW_H + 8);
            }
            uint32_t b[8][2];
#pragma unroll
            for (int nt = 0; nt < 8; nt++) {
                const __half* bp = Bs + (wn * 64 + nt * 8 + g) * SROW_H + kb + 2 * c4;
                b[nt][0] = *(const uint32_t*)bp;
                b[nt][1] = *(const uint32_t*)(bp + 8);
            }
#pragma unroll
            for (int mt = 0; mt < 4; mt++)
#pragma unroll
                for (int nt = 0; nt < 8; nt++)
                    HMMA(acc[mt][nt], a[mt][0], a[mt][1], a[mt][2], a[mt][3],
                         b[nt][0], b[nt][1]);
        }
        if (ci + 2 < KC) {
            int sn = st + 2; if (sn >= 3) sn -= 3;
            g1_load(smh + (size_t)sn * STAGE256, X, W, M, bm, ncol, (ci + 2) * 32, tid);
            asm volatile("cp.async.commit_group;" ::: "memory");
            asm volatile("cp.async.wait_group 1;" ::: "memory");
        } else {
            asm volatile("cp.async.wait_group 0;" ::: "memory");
        }
        __syncthreads();
        if (++st == 3) st = 0;
    }

#pragma unroll
    for (int mt = 0; mt < 4; mt++) {
        const int row = bm + wm * 64 + mt * 16 + g;
#pragma unroll
        for (int nt = 0; nt < 8; nt++) {
            const int col = ncol + wn * 64 + nt * 8 + 2 * c4;
            if (row < M)
                *(float2*)&C[(size_t)row * 1024 + col] = make_float2(acc[mt][nt][0], acc[mt][nt][1]);
            if (row + 8 < M)
                *(float2*)&C[(size_t)(row + 8) * 1024 + col] = make_float2(acc[mt][nt][2], acc[mt][nt][3]);
        }
    }
}

// ============================ merged per-level GEMM (fp16, d >= 7; R7 scalar version) ============================
#define HMMA_COMPUTE(As, Bs)                                                       \
    do {                                                                           \
        _Pragma("unroll")                                                          \
        for (int ks = 0; ks < 2; ks++) {                                           \
            const int kb = ks * 16;                                                \
            uint32_t a[2][4];                                                      \
            _Pragma("unroll")                                                      \
            for (int mt = 0; mt < 2; mt++) {                                       \
                const __half* ap = (As) + (wm * 32 + mt * 16 + g) * SROW_H + kb + 2 * c4; \
                a[mt][0] = *(const uint32_t*)ap;                                   \
                a[mt][1] = *(const uint32_t*)(ap + 8 * SROW_H);                    \
                a[mt][2] = *(const uint32_t*)(ap + 8);                             \
                a[mt][3] = *(const uint32_t*)(ap + 8 * SROW_H + 8);                \
            }                                                                      \
            uint32_t b[8][2];                                                      \
            _Pragma("unroll")                                                      \
            for (int nt = 0; nt < 8; nt++) {                                       \
                const __half* bp = (Bs) + (wn * 64 + nt * 8 + g) * SROW_H + kb + 2 * c4; \
                b[nt][0] = *(const uint32_t*)bp;                                   \
                b[nt][1] = *(const uint32_t*)(bp + 8);                             \
            }                                                                      \
            _Pragma("unroll")                                                      \
            for (int mt = 0; mt < 2; mt++)                                         \
                _Pragma("unroll")                                                  \
                for (int nt = 0; nt < 8; nt++)                                     \
                    HMMA(acc[mt][nt], a[mt][0], a[mt][1], a[mt][2], a[mt][3],      \
                         b[nt][0], b[nt][1]);                                      \
        }                                                                          \
    } while (0)

__global__ __launch_bounds__(256, 2)
void level_gemm_h(int S, int sc, int tiles_m_iou) {
    extern __shared__ __half smh[];

    const int tid  = threadIdx.x;
    const int wid  = tid >> 5;
    const int lane = tid & 31;
    const int wm = wid & 3, wn = wid >> 2;
    const int g  = lane >> 2, c4 = lane & 3;

    int t = blockIdx.x;
    const bool is_iou = (t < tiles_m_iou * 6);
    int tm, tn, ldc;
    const __half* Bsrc;
    float* C;
    if (is_iou) { tm = t / 6; tn = t - tm * 6; Bsrc = g_WIOUh + (size_t)tn * 128 * 256; C = g_PIOU; ldc = 768; }
    else { int t2 = t - tiles_m_iou * 6; tm = t2 >> 1; tn = t2 & 1; Bsrc = g_WFh + (size_t)tn * 128 * 256; C = g_PF; ldc = 256; }
    const int bm = tm * 128;

    const int r  = tid >> 1;           // 0..127 (A/B staging row)
    const int hq = (tid & 1) * 16;     // half offset 0 or 16

    float acc[2][8][4];
#pragma unroll
    for (int mt = 0; mt < 2; mt++)
#pragma unroll
        for (int nt = 0; nt < 8; nt++)
#pragma unroll
            for (int i = 0; i < 4; i++) acc[mt][nt][i] = 0.f;

    uint4 ua0, ua1;

#define LGH_LOAD_A(ci)                                                                    \
    do {                                                                                  \
        const int k0 = (ci) * 32;                                                         \
        if (is_iou) {                                                                     \
            const __half* pl = g_H16 + (size_t)(sc + 2 * (bm + r)) * 256 + k0 + hq;       \
            const __half* pr = pl + 256;                                                  \
            uint4 l0 = *(const uint4*)pl, l1 = *(const uint4*)(pl + 8);                   \
            uint4 r0_ = *(const uint4*)pr, r1_ = *(const uint4*)(pr + 8);                 \
            ua0.x = hadd2u(l0.x, r0_.x); ua0.y = hadd2u(l0.y, r0_.y);                     \
            ua0.z = hadd2u(l0.z, r0_.z); ua0.w = hadd2u(l0.w, r0_.w);                     \
            ua1.x = hadd2u(l1.x, r1_.x); ua1.y = hadd2u(l1.y, r1_.y);                     \
            ua1.z = hadd2u(l1.z, r1_.z); ua1.w = hadd2u(l1.w, r1_.w);                     \
        } else {                                                                          \
            const __half* p = g_H16 + (size_t)(sc + bm + r) * 256 + k0 + hq;              \
            ua0 = *(const uint4*)p; ua1 = *(const uint4*)(p + 8);                         \
        }                                                                                 \
    } while (0)

#define LGH_STORE_A(As)                                                                   \
    do {                                                                                  \
        *(uint4*)&(As)[r * SROW_H + hq]     = ua0;                                        \
        *(uint4*)&(As)[r * SROW_H + hq + 8] = ua1;                                        \
    } while (0)

#define LGH_CPASYNC_B(ci, Bs)                                                             \
    do {                                                                                  \
        const int k0 = (ci) * 32;                                                         \
        const __half* gb = Bsrc + (size_t)r * 256 + k0 + hq;                              \
        uint32_t sb = smem_u32(&(Bs)[r * SROW_H + hq]);                                   \
        asm volatile("cp.async.cg.shared.global [%0], [%1], 16;" :: "r"(sb), "l"(gb) : "memory"); \
        asm volatile("cp.async.cg.shared.global [%0], [%1], 16;" :: "r"(sb + 16u), "l"(gb + 8) : "memory"); \
    } while (0)

    // prologue: chunk 0
    LGH_LOAD_A(0);
    LGH_CPASYNC_B(0, smh + TILE_H);
    asm volatile("cp.async.commit_group;" ::: "memory");
    LGH_STORE_A(smh);
    asm volatile("cp.async.wait_group 0;" ::: "memory");
    __syncthreads();

    for (int ci = 0; ci < 8; ci++) {
        __half* bufn = smh + (size_t)((ci + 1) & 1) * STAGE_H;
        if (ci + 1 < 8) {
            LGH_LOAD_A(ci + 1);
            LGH_CPASYNC_B(ci + 1, bufn + TILE_H);
            asm volatile("cp.async.commit_group;" ::: "memory");
        }
        const __half* As = smh + (size_t)(ci & 1) * STAGE_H;
        const __half* Bs = As + TILE_H;
        HMMA_COMPUTE(As, Bs);
        __syncthreads();
        if (ci + 1 < 8) {
            LGH_STORE_A(bufn);
            asm volatile("cp.async.wait_group 0;" ::: "memory");
            __syncthreads();
        }
    }

#pragma unroll
    for (int mt = 0; mt < 2; mt++) {
        const int row = bm + wm * 32 + mt * 16 + g;
#pragma unroll
        for (int nt = 0; nt < 8; nt++) {
            const int col = tn * 128 + wn * 64 + nt * 8 + 2 * c4;
            *(float2*)&C[(size_t)row * ldc + col] = make_float2(acc[mt][nt][0], acc[mt][nt][1]);
            *(float2*)&C[(size_t)(row + 8) * ldc + col] = make_float2(acc[mt][nt][2], acc[mt][nt][3]);
        }
    }
#undef LGH_LOAD_A
#undef LGH_STORE_A
#undef LGH_CPASYNC_B
}

// ============================ epilogues ============================
__device__ __forceinline__ float sigmoidf_(float x) { return __fdividef(1.f, 1.f + __expf(-x)); }
__device__ __forceinline__ float ftanh_(float x) {
    float t = __expf(2.f * x);
    return 1.f - __fdividef(2.f, t + 1.f);
}
__device__ __forceinline__ float4 f4add(float4 a, float4 b) {
    return make_float4(a.x + b.x, a.y + b.y, a.z + b.z, a.w + b.w);
}
__device__ __forceinline__ void store_h16(int n, int q, float4 hn) {
    __half2 lo = __floats2half2_rn(hn.x, hn.y);
    __half2 hi = __floats2half2_rn(hn.z, hn.w);
    uint2 v = make_uint2(*reinterpret_cast<uint32_t*>(&lo), *reinterpret_cast<uint32_t*>(&hi));
    *(uint2*)&g_H16[(size_t)n * 256 + q] = v;
}

__global__ void leaf_epi(float* __restrict__ c, float* __restrict__ h) {
    const int j = threadIdx.x >> 6;
    const int q = (threadIdx.x & 63) * 4;
    const int n = LEAF_START + blockIdx.x * 4 + j;
    const float* pre = g_PRE + (size_t)n * 1024;
    float4 pi = f4add(*(const float4*)&pre[q],        *(const float4*)&g_BIO[q]);
    float4 po = f4add(*(const float4*)&pre[256 + q],  *(const float4*)&g_BIO[256 + q]);
    float4 pu = f4add(*(const float4*)&pre[512 + q],  *(const float4*)&g_BIO[512 + q]);
    float4 cn, hn;
#define GATE(X) do { \
        float iv = sigmoidf_(pi.X), ov = sigmoidf_(po.X), uv = ftanh_(pu.X); \
        float cv = iv * uv; cn.X = cv; hn.X = ov * ftanh_(cv); } while (0)
    GATE(x); GATE(y); GATE(z); GATE(w);
#undef GATE
    *(float4*)&c[(size_t)n * NMEM + q] = cn;
    *(float4*)&h[(size_t)n * NMEM + q] = hn;
    store_h16(n, q, hn);
}

__global__ void level_epi(float* __restrict__ c, float* __restrict__ h,
                          int start, int sc, int S) {
    const int j = threadIdx.x >> 6;
    const int q = (threadIdx.x & 63) * 4;
    const int r = blockIdx.x * 4 + j;
    const int n = start + r;
    const float* pre = g_PRE + (size_t)n * 1024;
    const float* piou = g_PIOU + (size_t)r * 768;
    float4 pi = f4add(f4add(*(const float4*)&piou[q],       *(const float4*)&pre[q]),       *(const float4*)&g_BIO[q]);
    float4 po = f4add(f4add(*(const float4*)&piou[256 + q], *(const float4*)&pre[256 + q]), *(const float4*)&g_BIO[256 + q]);
    float4 pu = f4add(f4add(*(const float4*)&piou[512 + q], *(const float4*)&pre[512 + q]), *(const float4*)&g_BIO[512 + q]);
    float4 fx = f4add(*(const float4*)&pre[768 + q], *(const float4*)&g_BF[q]);
    float4 pfl = f4add(*(const float4*)&g_PF[(size_t)(2 * r) * 256 + q], fx);
    float4 pfr = f4add(*(const float4*)&g_PF[(size_t)(2 * r + 1) * 256 + q], fx);
    float4 cl = *(const float4*)&c[(size_t)(sc + 2 * r) * NMEM + q];
    float4 cr = *(const float4*)&c[(size_t)(sc + 2 * r + 1) * NMEM + q];
    float4 cn, hn;
#define GATE(X) do { \
        float iv = sigmoidf_(pi.X), ov = sigmoidf_(po.X), uv = ftanh_(pu.X); \
        float fl = sigmoidf_(pfl.X), fr = sigmoidf_(pfr.X); \
        float cv = iv * uv + fl * cl.X + fr * cr.X; \
        cn.X = cv; hn.X = ov * ftanh_(cv); } while (0)
    GATE(x); GATE(y); GATE(z); GATE(w);
#undef GATE
    *(float4*)&c[(size_t)n * NMEM + q] = cn;
    *(float4*)&h[(size_t)n * NMEM + q] = hn;
    store_h16(n, q, hn);
}

// ============================ fused small levels (d <= 6, S <= 64) ============================
__global__ __launch_bounds__(256)
void fused_small(float* __restrict__ c, float* __restrict__ h, int start, int sc) {
    __shared__ float s_hsum[256], s_hl[256], s_hr[256];
    const int r = blockIdx.x, t = threadIdx.x;
    const int n = start + r;
    const int lc = sc + 2 * r;
    float hl = h[(size_t)lc * NMEM + t];
    float hr = h[(size_t)(lc + 1) * NMEM + t];
    s_hl[t] = hl; s_hr[t] = hr; s_hsum[t] = hl + hr;
    __syncthreads();

    const __half* w0 = g_WIOUh + (size_t)t * 256;
    const __half* w1 = w0 + 256 * 256;
    const __half* w2 = w1 + 256 * 256;
    const __half* wf = g_WFh + (size_t)t * 256;

    float di = 0.f, dq = 0.f, du = 0.f, dfl = 0.f, dfr = 0.f;
#pragma unroll 4
    for (int k = 0; k < 256; k += 8) {
        uint4 u0 = *(const uint4*)&w0[k];
        uint4 u1 = *(const uint4*)&w1[k];
        uint4 u2 = *(const uint4*)&w2[k];
        uint4 uf = *(const uint4*)&wf[k];
#pragma unroll
        for (int p = 0; p < 4; p++) {
            uint32_t b0 = (&u0.x)[p], b1 = (&u1.x)[p], b2 = (&u2.x)[p], bf = (&uf.x)[p];
            float2 f0 = __half22float2(*reinterpret_cast<__half2*>(&b0));
            float2 f1 = __half22float2(*reinterpret_cast<__half2*>(&b1));
            float2 f2 = __half22float2(*reinterpret_cast<__half2*>(&b2));
            float2 ff = __half22float2(*reinterpret_cast<__half2*>(&bf));
            float hs0 = s_hsum[k + 2 * p], hs1 = s_hsum[k + 2 * p + 1];
            float l0 = s_hl[k + 2 * p],   l1 = s_hl[k + 2 * p + 1];
            float r0 = s_hr[k + 2 * p],   r1 = s_hr[k + 2 * p + 1];
            di  = fmaf(f0.x, hs0, fmaf(f0.y, hs1, di));
            dq  = fmaf(f1.x, hs0, fmaf(f1.y, hs1, dq));
            du  = fmaf(f2.x, hs0, fmaf(f2.y, hs1, du));
            dfl = fmaf(ff.x, l0,  fmaf(ff.y, l1,  dfl));
            dfr = fmaf(ff.x, r0,  fmaf(ff.y, r1,  dfr));
        }
    }

    const float* pre = g_PRE + (size_t)n * 1024;
    float iv = sigmoidf_(di + pre[t]       + g_BIO[t]);
    float ov = sigmoidf_(dq + pre[256 + t] + g_BIO[256 + t]);
    float uv = ftanh_(   du + pre[512 + t] + g_BIO[512 + t]);
    float fx = pre[768 + t] + g_BF[t];
    float fl = sigmoidf_(dfl + fx);
    float fr = sigmoidf_(dfr + fx);
    float cl = c[(size_t)lc * NMEM + t];
    float cr = c[(size_t)(lc + 1) * NMEM + t];
    float cn = iv * uv + fl * cl + fr * cr;
    float hn = ov * ftanh_(cn);
    c[(size_t)n * NMEM + t] = cn;
    h[(size_t)n * NMEM + t] = hn;
    g_H16[(size_t)n * 256 + t] = __float2half_rn(hn);
}

// ============================ launcher ============================
extern "C" void kernel_launch(void* const* d_in, const int* in_sizes, int n_in,
                              void* d_out, int out_size) {
    const float* inputs = (const float*)d_in[0];
    const float* W_ioux = (const float*)d_in[1];
    const float* b_ioux = (const float*)d_in[2];
    const float* W_iouh = (const float*)d_in[3];
    const float* b_iouh = (const float*)d_in[4];
    const float* W_fx   = (const float*)d_in[5];
    const float* b_fx   = (const float*)d_in[6];
    const float* W_fh   = (const float*)d_in[7];
    const float* b_fh   = (const float*)d_in[8];
    (void)in_sizes; (void)n_in; (void)out_size;

    float* c = (float*)d_out;                   // out[0] = c  [N,256]
    float* h = c + (size_t)NN * NMEM;           // out[1] = h  [N,256]

    float* pPRE;
    __half *pX16, *pW1h;
    cudaGetSymbolAddress((void**)&pPRE, g_PRE);
    cudaGetSymbolAddress((void**)&pX16, g_X16);
    cudaGetSymbolAddress((void**)&pW1h, g_W1h);

    const int SMEM1 = 3 * STAGE256 * 2;  // 92160 B (3-stage, A128+B256)
    const int SMEML = 2 * STAGE_H * 2;   // 40960 B (2-stage)
    cudaFuncSetAttribute(gemm1_h,      cudaFuncAttributeMaxDynamicSharedMemorySize, SMEM1);
    cudaFuncSetAttribute(level_gemm_h, cudaFuncAttributeMaxDynamicSharedMemorySize, SMEML);

    conv_x<<<(NN * 160 + 255) / 256, 256>>>(inputs);
    build_w1h<<<(1024 * 320 + 255) / 256, 256>>>(W_ioux, W_fx);
    build_misch<<<(263168 + 255) / 256, 256>>>(W_iouh, W_fh, b_ioux, b_iouh, b_fx, b_fh);

    // gemm1a: iou cols (0..767) for ALL nodes  (3 col tiles of 256)
    {
        dim3 grd(3, 512);
        gemm1_h<<<grd, 256, SMEM1>>>(pX16, pW1h, pPRE, NN, 0);
    }
    // gemm1b: fx cols (768..1023) for INTERNAL nodes only (1 col tile of 256)
    {
        dim3 grd(1, 256);
        gemm1_h<<<grd, 256, SMEM1>>>(pX16, pW1h, pPRE, LEAF_START, 768);
    }

    // leaves (depth 15)
    leaf_epi<<<8192, 256>>>(c, h);

    // big internal levels (S multiple of 128)
    for (int d = 14; d >= 7; --d) {
        const int S = 1 << d;
        const int start = S - 1;
        const int sc = 2 * S - 1;
        const int tiles_m_iou = S / 128;
        const int gx = tiles_m_iou * 6 + (2 * S / 128) * 2;
        level_gemm_h<<<gx, 256, SMEML>>>(S, sc, tiles_m_iou);
        level_epi<<<S / 4, 256>>>(c, h, start, sc, S);
    }

    // small levels (d <= 6): fused GEMM + epilogue, one launch per level
    for (int d = 6; d >= 0; --d) {
        const int S = 1 << d;
        fused_small<<<S, 256>>>(c, h, S - 1, 2 * S - 1);
    }
}

// round 14
// speedup vs baseline: 1.0920x; 1.0920x over previous
#include <cuda_runtime.h>
#include <cuda_fp16.h>
#include <math.h>
#include <cstdint>

#define NN 65535            // total nodes
#define LEAF_START 32767
#define NMEM 256

// ---- scratch (device globals; no allocation allowed) ----
__device__ float  g_PRE[(size_t)NN * 1024];      // [N,1024]: 0..767 x@W_ioux^T, 768..1023 x@W_fx^T
__device__ float  g_PIOU[(size_t)16384 * 768];   // per-level iou recurrent term [S,768]
__device__ float  g_PF[(size_t)32768 * 256];     // per-level child f-projections [2S,256]
__device__ __half g_X16[(size_t)NN * 320];       // inputs fp16, K padded 300->320
__device__ __half g_W1h[1024 * 320];             // gemm1 B fp16 [n][k]
__device__ __half g_WIOUh[768 * 256];            // W_iouh fp16 [n][k]
__device__ __half g_WFh[256 * 256];              // W_fh fp16 [n][k]
__device__ __half g_H16[(size_t)NN * 256];       // h in fp16
__device__ float  g_BIO[768];                    // b_ioux + b_iouh
__device__ float  g_BF[256];                     // b_fx + b_fh

// ============================ helpers ============================
__device__ __forceinline__ uint32_t smem_u32(const void* p) {
    uint32_t a;
    asm("{ .reg .u64 t; cvta.to.shared.u64 t, %1; cvt.u32.u64 %0, t; }" : "=r"(a) : "l"(p));
    return a;
}
__device__ __forceinline__ uint32_t hadd2u(uint32_t a, uint32_t b) {
    __half2 r = __hadd2(*reinterpret_cast<__half2*>(&a), *reinterpret_cast<__half2*>(&b));
    return *reinterpret_cast<uint32_t*>(&r);
}

// ============================ conversion / repacking ============================
__global__ void conv_x(const float* __restrict__ inputs) {
    int idx = blockIdx.x * blockDim.x + threadIdx.x;     // over 65535*160 half2
    if (idx >= NN * 160) return;
    int row = idx / 160, c2 = idx - row * 160;
    int k = 2 * c2;
    __half2 v;
    if (k < 300) {
        float2 f = *(const float2*)&inputs[(size_t)row * 300 + k];
        v = __floats2half2_rn(f.x, f.y);
    } else {
        v = __floats2half2_rn(0.f, 0.f);
    }
    *(__half2*)&g_X16[(size_t)row * 320 + k] = v;
}

__global__ void build_w1h(const float* __restrict__ W_ioux, const float* __restrict__ W_fx) {
    int idx = blockIdx.x * blockDim.x + threadIdx.x;
    if (idx >= 1024 * 320) return;
    int j = idx / 320, k = idx - j * 320;
    float v = 0.f;
    if (k < 300) v = (j < 768) ? W_ioux[j * 300 + k] : W_fx[(j - 768) * 300 + k];
    g_W1h[idx] = __float2half_rn(v);
}

__global__ void build_misch(const float* __restrict__ W_iouh, const float* __restrict__ W_fh,
                            const float* __restrict__ b_ioux, const float* __restrict__ b_iouh,
                            const float* __restrict__ b_fx, const float* __restrict__ b_fh) {
    int i = blockIdx.x * blockDim.x + threadIdx.x;
    if (i < 196608)       g_WIOUh[i] = __float2half_rn(W_iouh[i]);
    else if (i < 262144)  g_WFh[i - 196608] = __float2half_rn(W_fh[i - 196608]);
    else if (i < 262912)  { int j = i - 262144; g_BIO[j] = b_ioux[j] + b_iouh[j]; }
    else if (i < 263168)  { int j = i - 262912; g_BF[j]  = b_fx[j]  + b_fh[j];  }
}

// ============================ smem tiling constants (fp16) ============================
#define SROW_H 40                       // 32 + 8 pad halves per smem row (80 B, conflict-free)
#define TILE_H (128 * SROW_H)           // one 128x32-half tile
#define STAGE_H (2 * TILE_H)            // A + B per stage

// fp16 mma: D += A(16x16) * B^T(8x16)
#define HMMA(accp, a0, a1, a2, a3, b0, b1)                                         \
    asm volatile(                                                                  \
        "mma.sync.aligned.m16n8k16.row.col.f32.f16.f16.f32 "                       \
        "{%0,%1,%2,%3}, {%4,%5,%6,%7}, {%8,%9}, {%0,%1,%2,%3};"                    \
        : "+f"((accp)[0]), "+f"((accp)[1]), "+f"((accp)[2]), "+f"((accp)[3])       \
        : "r"(a0), "r"(a1), "r"(a2), "r"(a3), "r"(b0), "r"(b1))

// ============================ gemm1: X16[M,320] @ W1h[.,320]^T -> PRE fp32 ============================
// R7-exact config: 128 threads, 2x2 warps, 64x64 warp tiles, 3-stage cp.async, scalar LDS.
__device__ __forceinline__ void g1_load(__half* dst, const __half* __restrict__ X,
                                        const __half* __restrict__ W,
                                        int M, int bm, int ncol, int k0, int tid) {
    const int r0 = tid >> 2;          // 0..31
    const int cq = (tid & 3) * 8;     // half offset: 0,8,16,24 (16B chunks)
#pragma unroll
    for (int i = 0; i < 4; i++) {
        const int row = r0 + i * 32;
        {
            const bool ok = (bm + row) < M;
            const __half* ga = ok ? (X + (size_t)(bm + row) * 320 + k0 + cq) : X;
            uint32_t sa = smem_u32(dst + row * SROW_H + cq);
            uint32_t sz = ok ? 16u : 0u;
            asm volatile("cp.async.cg.shared.global [%0], [%1], 16, %2;"
                         :: "r"(sa), "l"(ga), "r"(sz) : "memory");
        }
        {
            const __half* gb = W + (size_t)(ncol + row) * 320 + k0 + cq;
            uint32_t sb = smem_u32(dst + TILE_H + row * SROW_H + cq);
            asm volatile("cp.async.cg.shared.global [%0], [%1], 16;"
                         :: "r"(sb), "l"(gb) : "memory");
        }
    }
}

__global__ __launch_bounds__(128, 2)
void gemm1_h(const __half* __restrict__ X, const __half* __restrict__ W,
             float* __restrict__ C, int M, int bn0) {
    extern __shared__ __half smh[];
    const int tid  = threadIdx.x;
    const int wid  = tid >> 5;
    const int lane = tid & 31;
    const int wm = wid & 1, wn = wid >> 1;     // 2x2 warp grid, 64x64 warp tiles
    const int g  = lane >> 2, c4 = lane & 3;
    const int bm = blockIdx.y * 128;           // grid: x = col tiles (fast), y = row tiles
    const int ncol = bn0 + blockIdx.x * 128;
    const int KC = 10;

    float acc[4][8][4];
#pragma unroll
    for (int mt = 0; mt < 4; mt++)
#pragma unroll
        for (int nt = 0; nt < 8; nt++)
#pragma unroll
            for (int i = 0; i < 4; i++) acc[mt][nt][i] = 0.f;

    g1_load(smh, X, W, M, bm, ncol, 0, tid);
    asm volatile("cp.async.commit_group;" ::: "memory");
    g1_load(smh + STAGE_H, X, W, M, bm, ncol, 32, tid);
    asm volatile("cp.async.commit_group;" ::: "memory");
    asm volatile("cp.async.wait_group 1;" ::: "memory");
    __syncthreads();

    int st = 0;
    for (int ci = 0; ci < KC; ci++) {
        const __half* As = smh + (size_t)st * STAGE_H;
        const __half* Bs = As + TILE_H;
#pragma unroll
        for (int ks = 0; ks < 2; ks++) {
            const int kb = ks * 16;
            uint32_t a[4][4];
#pragma unroll
            for (int mt = 0; mt < 4; mt++) {
                const __half* ap = As + (wm * 64 + mt * 16 + g) * SROW_H + kb + 2 * c4;
                a[mt][0] = *(const uint32_t*)ap;
                a[mt][1] = *(const uint32_t*)(ap + 8 * SROW_H);
                a[mt][2] = *(const uint32_t*)(ap + 8);
                a[mt][3] = *(const uint32_t*)(ap + 8 * SROW_H + 8);
            }
            uint32_t b[8][2];
#pragma unroll
            for (int nt = 0; nt < 8; nt++) {
                const __half* bp = Bs + (wn * 64 + nt * 8 + g) * SROW_H + kb + 2 * c4;
                b[nt][0] = *(const uint32_t*)bp;
                b[nt][1] = *(const uint32_t*)(bp + 8);
            }
#pragma unroll
            for (int mt = 0; mt < 4; mt++)
#pragma unroll
                for (int nt = 0; nt < 8; nt++)
                    HMMA(acc[mt][nt], a[mt][0], a[mt][1], a[mt][2], a[mt][3],
                         b[nt][0], b[nt][1]);
        }
        if (ci + 2 < KC) {
            int sn = st + 2; if (sn >= 3) sn -= 3;
            g1_load(smh + (size_t)sn * STAGE_H, X, W, M, bm, ncol, (ci + 2) * 32, tid);
            asm volatile("cp.async.commit_group;" ::: "memory");
            asm volatile("cp.async.wait_group 1;" ::: "memory");
        } else {
            asm volatile("cp.async.wait_group 0;" ::: "memory");
        }
        __syncthreads();
        if (++st == 3) st = 0;
    }

#pragma unroll
    for (int mt = 0; mt < 4; mt++) {
        const int row = bm + wm * 64 + mt * 16 + g;
#pragma unroll
        for (int nt = 0; nt < 8; nt++) {
            const int col = ncol + wn * 64 + nt * 8 + 2 * c4;
            if (row < M)
                *(float2*)&C[(size_t)row * 1024 + col] = make_float2(acc[mt][nt][0], acc[mt][nt][1]);
            if (row + 8 < M)
                *(float2*)&C[(size_t)(row + 8) * 1024 + col] = make_float2(acc[mt][nt][2], acc[mt][nt][3]);
        }
    }
}

// ============================ merged per-level GEMM (fp16, d >= 7; R7 scalar version) ============================
#define HMMA_COMPUTE(As, Bs)                                                       \
    do {                                                                           \
        _Pragma("unroll")                                                          \
        for (int ks = 0; ks < 2; ks++) {                                           \
            const int kb = ks * 16;                                                \
            uint32_t a[2][4];                                                      \
            _Pragma("unroll")                                                      \
            for (int mt = 0; mt < 2; mt++) {                                       \
                const __half* ap = (As) + (wm * 32 + mt * 16 + g) * SROW_H + kb + 2 * c4; \
                a[mt][0] = *(const uint32_t*)ap;                                   \
                a[mt][1] = *(const uint32_t*)(ap + 8 * SROW_H);                    \
                a[mt][2] = *(const uint32_t*)(ap + 8);                             \
                a[mt][3] = *(const uint32_t*)(ap + 8 * SROW_H + 8);                \
            }                                                                      \
            uint32_t b[8][2];                                                      \
            _Pragma("unroll")                                                      \
            for (int nt = 0; nt < 8; nt++) {                                       \
                const __half* bp = (Bs) + (wn * 64 + nt * 8 + g) * SROW_H + kb + 2 * c4; \
                b[nt][0] = *(const uint32_t*)bp;                                   \
                b[nt][1] = *(const uint32_t*)(bp + 8);                             \
            }                                                                      \
            _Pragma("unroll")                                                      \
            for (int mt = 0; mt < 2; mt++)                                         \
                _Pragma("unroll")                                                  \
                for (int nt = 0; nt < 8; nt++)                                     \
                    HMMA(acc[mt][nt], a[mt][0], a[mt][1], a[mt][2], a[mt][3],      \
                         b[nt][0], b[nt][1]);                                      \
        }                                                                          \
    } while (0)

__global__ __launch_bounds__(256, 2)
void level_gemm_h(int S, int sc, int tiles_m_iou) {
    extern __shared__ __half smh[];

    const int tid  = threadIdx.x;
    const int wid  = tid >> 5;
    const int lane = tid & 31;
    const int wm = wid & 3, wn = wid >> 2;
    const int g  = lane >> 2, c4 = lane & 3;

    int t = blockIdx.x;
    const bool is_iou = (t < tiles_m_iou * 6);
    int tm, tn, ldc;
    const __half* Bsrc;
    float* C;
    if (is_iou) { tm = t / 6; tn = t - tm * 6; Bsrc = g_WIOUh + (size_t)tn * 128 * 256; C = g_PIOU; ldc = 768; }
    else { int t2 = t - tiles_m_iou * 6; tm = t2 >> 1; tn = t2 & 1; Bsrc = g_WFh + (size_t)tn * 128 * 256; C = g_PF; ldc = 256; }
    const int bm = tm * 128;

    const int r  = tid >> 1;           // 0..127 (A/B staging row)
    const int hq = (tid & 1) * 16;     // half offset 0 or 16

    float acc[2][8][4];
#pragma unroll
    for (int mt = 0; mt < 2; mt++)
#pragma unroll
        for (int nt = 0; nt < 8; nt++)
#pragma unroll
            for (int i = 0; i < 4; i++) acc[mt][nt][i] = 0.f;

    uint4 ua0, ua1;

#define LGH_LOAD_A(ci)                                                                    \
    do {                                                                                  \
        const int k0 = (ci) * 32;                                                         \
        if (is_iou) {                                                                     \
            const __half* pl = g_H16 + (size_t)(sc + 2 * (bm + r)) * 256 + k0 + hq;       \
            const __half* pr = pl + 256;                                                  \
            uint4 l0 = *(const uint4*)pl, l1 = *(const uint4*)(pl + 8);                   \
            uint4 r0_ = *(const uint4*)pr, r1_ = *(const uint4*)(pr + 8);                 \
            ua0.x = hadd2u(l0.x, r0_.x); ua0.y = hadd2u(l0.y, r0_.y);                     \
            ua0.z = hadd2u(l0.z, r0_.z); ua0.w = hadd2u(l0.w, r0_.w);                     \
            ua1.x = hadd2u(l1.x, r1_.x); ua1.y = hadd2u(l1.y, r1_.y);                     \
            ua1.z = hadd2u(l1.z, r1_.z); ua1.w = hadd2u(l1.w, r1_.w);                     \
        } else {                                                                          \
            const __half* p = g_H16 + (size_t)(sc + bm + r) * 256 + k0 + hq;              \
            ua0 = *(const uint4*)p; ua1 = *(const uint4*)(p + 8);                         \
        }                                                                                 \
    } while (0)

#define LGH_STORE_A(As)                                                                   \
    do {                                                                                  \
        *(uint4*)&(As)[r * SROW_H + hq]     = ua0;                                        \
        *(uint4*)&(As)[r * SROW_H + hq + 8] = ua1;                                        \
    } while (0)

#define LGH_CPASYNC_B(ci, Bs)                                                             \
    do {                                                                                  \
        const int k0 = (ci) * 32;                                                         \
        const __half* gb = Bsrc + (size_t)r * 256 + k0 + hq;                              \
        uint32_t sb = smem_u32(&(Bs)[r * SROW_H + hq]);                                   \
        asm volatile("cp.async.cg.shared.global [%0], [%1], 16;" :: "r"(sb), "l"(gb) : "memory"); \
        asm volatile("cp.async.cg.shared.global [%0], [%1], 16;" :: "r"(sb + 16u), "l"(gb + 8) : "memory"); \
    } while (0)

    // prologue: chunk 0
    LGH_LOAD_A(0);
    LGH_CPASYNC_B(0, smh + TILE_H);
    asm volatile("cp.async.commit_group;" ::: "memory");
    LGH_STORE_A(smh);
    asm volatile("cp.async.wait_group 0;" ::: "memory");
    __syncthreads();

    for (int ci = 0; ci < 8; ci++) {
        __half* bufn = smh + (size_t)((ci + 1) & 1) * STAGE_H;
        if (ci + 1 < 8) {
            LGH_LOAD_A(ci + 1);
            LGH_CPASYNC_B(ci + 1, bufn + TILE_H);
            asm volatile("cp.async.commit_group;" ::: "memory");
        }
        const __half* As = smh + (size_t)(ci & 1) * STAGE_H;
        const __half* Bs = As + TILE_H;
        HMMA_COMPUTE(As, Bs);
        __syncthreads();
        if (ci + 1 < 8) {
            LGH_STORE_A(bufn);
            asm volatile("cp.async.wait_group 0;" ::: "memory");
            __syncthreads();
        }
    }

#pragma unroll
    for (int mt = 0; mt < 2; mt++) {
        const int row = bm + wm * 32 + mt * 16 + g;
#pragma unroll
        for (int nt = 0; nt < 8; nt++) {
            const int col = tn * 128 + wn * 64 + nt * 8 + 2 * c4;
            *(float2*)&C[(size_t)row * ldc + col] = make_float2(acc[mt][nt][0], acc[mt][nt][1]);
            *(float2*)&C[(size_t)(row + 8) * ldc + col] = make_float2(acc[mt][nt][2], acc[mt][nt][3]);
        }
    }
#undef LGH_LOAD_A
#undef LGH_STORE_A
#undef LGH_CPASYNC_B
}

// ============================ epilogues ============================
__device__ __forceinline__ float sigmoidf_(float x) { return __fdividef(1.f, 1.f + __expf(-x)); }
__device__ __forceinline__ float ftanh_(float x) {
    float t = __expf(2.f * x);
    return 1.f - __fdividef(2.f, t + 1.f);
}
__device__ __forceinline__ float4 f4add(float4 a, float4 b) {
    return make_float4(a.x + b.x, a.y + b.y, a.z + b.z, a.w + b.w);
}
__device__ __forceinline__ void store_h16(int n, int q, float4 hn) {
    __half2 lo = __floats2half2_rn(hn.x, hn.y);
    __half2 hi = __floats2half2_rn(hn.z, hn.w);
    uint2 v = make_uint2(*reinterpret_cast<uint32_t*>(&lo), *reinterpret_cast<uint32_t*>(&hi));
    *(uint2*)&g_H16[(size_t)n * 256 + q] = v;
}

__global__ void leaf_epi(float* __restrict__ c, float* __restrict__ h) {
    const int j = threadIdx.x >> 6;
    const int q = (threadIdx.x & 63) * 4;
    const int n = LEAF_START + blockIdx.x * 4 + j;
    const float* pre = g_PRE + (size_t)n * 1024;
    float4 pi = f4add(*(const float4*)&pre[q],        *(const float4*)&g_BIO[q]);
    float4 po = f4add(*(const float4*)&pre[256 + q],  *(const float4*)&g_BIO[256 + q]);
    float4 pu = f4add(*(const float4*)&pre[512 + q],  *(const float4*)&g_BIO[512 + q]);
    float4 cn, hn;
#define GATE(X) do { \
        float iv = sigmoidf_(pi.X), ov = sigmoidf_(po.X), uv = ftanh_(pu.X); \
        float cv = iv * uv; cn.X = cv; hn.X = ov * ftanh_(cv); } while (0)
    GATE(x); GATE(y); GATE(z); GATE(w);
#undef GATE
    *(float4*)&c[(size_t)n * NMEM + q] = cn;
    *(float4*)&h[(size_t)n * NMEM + q] = hn;
    store_h16(n, q, hn);
}

__global__ void level_epi(float* __restrict__ c, float* __restrict__ h,
                          int start, int sc, int S) {
    const int j = threadIdx.x >> 6;
    const int q = (threadIdx.x & 63) * 4;
    const int r = blockIdx.x * 4 + j;
    const int n = start + r;
    const float* pre = g_PRE + (size_t)n * 1024;
    const float* piou = g_PIOU + (size_t)r * 768;
    float4 pi = f4add(f4add(*(const float4*)&piou[q],       *(const float4*)&pre[q]),       *(const float4*)&g_BIO[q]);
    float4 po = f4add(f4add(*(const float4*)&piou[256 + q], *(const float4*)&pre[256 + q]), *(const float4*)&g_BIO[256 + q]);
    float4 pu = f4add(f4add(*(const float4*)&piou[512 + q], *(const float4*)&pre[512 + q]), *(const float4*)&g_BIO[512 + q]);
    float4 fx = f4add(*(const float4*)&pre[768 + q], *(const float4*)&g_BF[q]);
    float4 pfl = f4add(*(const float4*)&g_PF[(size_t)(2 * r) * 256 + q], fx);
    float4 pfr = f4add(*(const float4*)&g_PF[(size_t)(2 * r + 1) * 256 + q], fx);
    float4 cl = *(const float4*)&c[(size_t)(sc + 2 * r) * NMEM + q];
    float4 cr = *(const float4*)&c[(size_t)(sc + 2 * r + 1) * NMEM + q];
    float4 cn, hn;
#define GATE(X) do { \
        float iv = sigmoidf_(pi.X), ov = sigmoidf_(po.X), uv = ftanh_(pu.X); \
        float fl = sigmoidf_(pfl.X), fr = sigmoidf_(pfr.X); \
        float cv = iv * uv + fl * cl.X + fr * cr.X; \
        cn.X = cv; hn.X = ov * ftanh_(cv); } while (0)
    GATE(x); GATE(y); GATE(z); GATE(w);
#undef GATE
    *(float4*)&c[(size_t)n * NMEM + q] = cn;
    *(float4*)&h[(size_t)n * NMEM + q] = hn;
    store_h16(n, q, hn);
}

// ============================ fused small levels (d <= 6, S <= 64) ============================
__global__ __launch_bounds__(256)
void fused_small(float* __restrict__ c, float* __restrict__ h, int start, int sc) {
    __shared__ float s_hsum[256], s_hl[256], s_hr[256];
    const int r = blockIdx.x, t = threadIdx.x;
    const int n = start + r;
    const int lc = sc + 2 * r;
    float hl = h[(size_t)lc * NMEM + t];
    float hr = h[(size_t)(lc + 1) * NMEM + t];
    s_hl[t] = hl; s_hr[t] = hr; s_hsum[t] = hl + hr;
    __syncthreads();

    const __half* w0 = g_WIOUh + (size_t)t * 256;
    const __half* w1 = w0 + 256 * 256;
    const __half* w2 = w1 + 256 * 256;
    const __half* wf = g_WFh + (size_t)t * 256;

    float di = 0.f, dq = 0.f, du = 0.f, dfl = 0.f, dfr = 0.f;
#pragma unroll 4
    for (int k = 0; k < 256; k += 8) {
        uint4 u0 = *(const uint4*)&w0[k];
        uint4 u1 = *(const uint4*)&w1[k];
        uint4 u2 = *(const uint4*)&w2[k];
        uint4 uf = *(const uint4*)&wf[k];
#pragma unroll
        for (int p = 0; p < 4; p++) {
            uint32_t b0 = (&u0.x)[p], b1 = (&u1.x)[p], b2 = (&u2.x)[p], bf = (&uf.x)[p];
            float2 f0 = __half22float2(*reinterpret_cast<__half2*>(&b0));
            float2 f1 = __half22float2(*reinterpret_cast<__half2*>(&b1));
            float2 f2 = __half22float2(*reinterpret_cast<__half2*>(&b2));
            float2 ff = __half22float2(*reinterpret_cast<__half2*>(&bf));
            float hs0 = s_hsum[k + 2 * p], hs1 = s_hsum[k + 2 * p + 1];
            float l0 = s_hl[k + 2 * p],   l1 = s_hl[k + 2 * p + 1];
            float r0 = s_hr[k + 2 * p],   r1 = s_hr[k + 2 * p + 1];
            di  = fmaf(f0.x, hs0, fmaf(f0.y, hs1, di));
            dq  = fmaf(f1.x, hs0, fmaf(f1.y, hs1, dq));
            du  = fmaf(f2.x, hs0, fmaf(f2.y, hs1, du));
            dfl = fmaf(ff.x, l0,  fmaf(ff.y, l1,  dfl));
            dfr = fmaf(ff.x, r0,  fmaf(ff.y, r1,  dfr));
        }
    }

    const float* pre = g_PRE + (size_t)n * 1024;
    float iv = sigmoidf_(di + pre[t]       + g_BIO[t]);
    float ov = sigmoidf_(dq + pre[256 + t] + g_BIO[256 + t]);
    float uv = ftanh_(   du + pre[512 + t] + g_BIO[512 + t]);
    float fx = pre[768 + t] + g_BF[t];
    float fl = sigmoidf_(dfl + fx);
    float fr = sigmoidf_(dfr + fx);
    float cl = c[(size_t)lc * NMEM + t];
    float cr = c[(size_t)(lc + 1) * NMEM + t];
    float cn = iv * uv + fl * cl + fr * cr;
    float hn = ov * ftanh_(cn);
    c[(size_t)n * NMEM + t] = cn;
    h[(size_t)n * NMEM + t] = hn;
    g_H16[(size_t)n * 256 + t] = __float2half_rn(hn);
}

// ============================ launcher ============================
extern "C" void kernel_launch(void* const* d_in, const int* in_sizes, int n_in,
                              void* d_out, int out_size) {
    const float* inputs = (const float*)d_in[0];
    const float* W_ioux = (const float*)d_in[1];
    const float* b_ioux = (const float*)d_in[2];
    const float* W_iouh = (const float*)d_in[3];
    const float* b_iouh = (const float*)d_in[4];
    const float* W_fx   = (const float*)d_in[5];
    const float* b_fx   = (const float*)d_in[6];
    const float* W_fh   = (const float*)d_in[7];
    const float* b_fh   = (const float*)d_in[8];
    (void)in_sizes; (void)n_in; (void)out_size;

    float* c = (float*)d_out;                   // out[0] = c  [N,256]
    float* h = c + (size_t)NN * NMEM;           // out[1] = h  [N,256]

    float* pPRE;
    __half *pX16, *pW1h;
    cudaGetSymbolAddress((void**)&pPRE, g_PRE);
    cudaGetSymbolAddress((void**)&pX16, g_X16);
    cudaGetSymbolAddress((void**)&pW1h, g_W1h);

    const int SMEM1 = 3 * STAGE_H * 2;   // 61440 B (3-stage fp16)
    const int SMEML = 2 * STAGE_H * 2;   // 40960 B (2-stage fp16)
    cudaFuncSetAttribute(gemm1_h,      cudaFuncAttributeMaxDynamicSharedMemorySize, SMEM1);
    cudaFuncSetAttribute(level_gemm_h, cudaFuncAttributeMaxDynamicSharedMemorySize, SMEML);

    conv_x<<<(NN * 160 + 255) / 256, 256>>>(inputs);
    build_w1h<<<(1024 * 320 + 255) / 256, 256>>>(W_ioux, W_fx);
    build_misch<<<(263168 + 255) / 256, 256>>>(W_iouh, W_fh, b_ioux, b_iouh, b_fx, b_fh);

    // gemm1a: iou cols (0..767) for ALL nodes  (6 col tiles of 128)
    {
        dim3 grd(6, 512);
        gemm1_h<<<grd, 128, SMEM1>>>(pX16, pW1h, pPRE, NN, 0);
    }
    // gemm1b: fx cols (768..1023) for INTERNAL nodes only (leaves' fx is dead work)
    {
        dim3 grd(2, 256);
        gemm1_h<<<grd, 128, SMEM1>>>(pX16, pW1h, pPRE, LEAF_START, 768);
    }

    // leaves (depth 15)
    leaf_epi<<<8192, 256>>>(c, h);

    // big internal levels (S multiple of 128)
    for (int d = 14; d >= 7; --d) {
        const int S = 1 << d;
        const int start = S - 1;
        const int sc = 2 * S - 1;
        const int tiles_m_iou = S / 128;
        const int gx = tiles_m_iou * 6 + (2 * S / 128) * 2;
        level_gemm_h<<<gx, 256, SMEML>>>(S, sc, tiles_m_iou);
        level_epi<<<S / 4, 256>>>(c, h, start, sc, S);
    }

    // small levels (d <= 6): fused GEMM + epilogue, one launch per level
    for (int d = 6; d >= 0; --d) {
        const int S = 1 << d;
        fused_small<<<S, 256>>>(c, h, S - 1, 2 * S - 1);
    }
}

// round 17
// speedup vs baseline: 1.1529x; 1.0557x over previous
#include <cuda_runtime.h>
#include <cuda_fp16.h>
#include <math.h>
#include <cstdint>

#define NN 65535            // total nodes
#define LEAF_START 32767
#define NMEM 256

// ---- scratch (device globals; no allocation allowed) ----
__device__ __half g_PRE16[(size_t)NN * 1024];    // [N,1024] fp16: 0..767 x@W_ioux^T, 768..1023 x@W_fx^T
__device__ __half g_PIOU16[(size_t)16384 * 768]; // per-level iou recurrent term [S,768] fp16
__device__ __half g_PF16[(size_t)32768 * 256];   // per-level child f-projections [2S,256] fp16
__device__ __half g_X16[(size_t)NN * 320];       // inputs fp16, K padded 300->320
__device__ __half g_W1h[1024 * 320];             // gemm1 B fp16 [n][k]
__device__ __half g_WIOUh[768 * 256];            // W_iouh fp16 [n][k]
__device__ __half g_WFh[256 * 256];              // W_fh fp16 [n][k]
__device__ __half g_H16[(size_t)NN * 256];       // h in fp16
__device__ float  g_BIO[768];                    // b_ioux + b_iouh
__device__ float  g_BF[256];                     // b_fx + b_fh

// ============================ helpers ============================
__device__ __forceinline__ uint32_t smem_u32(const void* p) {
    uint32_t a;
    asm("{ .reg .u64 t; cvta.to.shared.u64 t, %1; cvt.u32.u64 %0, t; }" : "=r"(a) : "l"(p));
    return a;
}
__device__ __forceinline__ uint32_t hadd2u(uint32_t a, uint32_t b) {
    __half2 r = __hadd2(*reinterpret_cast<__half2*>(&a), *reinterpret_cast<__half2*>(&b));
    return *reinterpret_cast<uint32_t*>(&r);
}
// load 4 consecutive halves (8B aligned) -> float4
__device__ __forceinline__ float4 ld_h4(const __half* p) {
    uint2 v = *(const uint2*)p;
    float2 lo = __half22float2(*reinterpret_cast<__half2*>(&v.x));
    float2 hi = __half22float2(*reinterpret_cast<__half2*>(&v.y));
    return make_float4(lo.x, lo.y, hi.x, hi.y);
}

// ============================ conversion / repacking ============================
__global__ void conv_x(const float* __restrict__ inputs) {
    int idx = blockIdx.x * blockDim.x + threadIdx.x;     // over 65535*160 half2
    if (idx >= NN * 160) return;
    int row = idx / 160, c2 = idx - row * 160;
    int k = 2 * c2;
    __half2 v;
    if (k < 300) {
        float2 f = *(const float2*)&inputs[(size_t)row * 300 + k];
        v = __floats2half2_rn(f.x, f.y);
    } else {
        v = __floats2half2_rn(0.f, 0.f);
    }
    *(__half2*)&g_X16[(size_t)row * 320 + k] = v;
}

__global__ void build_w1h(const float* __restrict__ W_ioux, const float* __restrict__ W_fx) {
    int idx = blockIdx.x * blockDim.x + threadIdx.x;
    if (idx >= 1024 * 320) return;
    int j = idx / 320, k = idx - j * 320;
    float v = 0.f;
    if (k < 300) v = (j < 768) ? W_ioux[j * 300 + k] : W_fx[(j - 768) * 300 + k];
    g_W1h[idx] = __float2half_rn(v);
}

__global__ void build_misch(const float* __restrict__ W_iouh, const float* __restrict__ W_fh,
                            const float* __restrict__ b_ioux, const float* __restrict__ b_iouh,
                            const float* __restrict__ b_fx, const float* __restrict__ b_fh) {
    int i = blockIdx.x * blockDim.x + threadIdx.x;
    if (i < 196608)       g_WIOUh[i] = __float2half_rn(W_iouh[i]);
    else if (i < 262144)  g_WFh[i - 196608] = __float2half_rn(W_fh[i - 196608]);
    else if (i < 262912)  { int j = i - 262144; g_BIO[j] = b_ioux[j] + b_iouh[j]; }
    else if (i < 263168)  { int j = i - 262912; g_BF[j]  = b_fx[j]  + b_fh[j];  }
}

// ============================ smem tiling constants (fp16) ============================
#define SROW_H 40                       // 32 + 8 pad halves per smem row (80 B, conflict-free)
#define TILE_H (128 * SROW_H)           // one 128x32-half tile
#define STAGE_H (2 * TILE_H)            // A + B per stage

// fp16 mma: D += A(16x16) * B^T(8x16)
#define HMMA(accp, a0, a1, a2, a3, b0, b1)                                         \
    asm volatile(                                                                  \
        "mma.sync.aligned.m16n8k16.row.col.f32.f16.f16.f32 "                       \
        "{%0,%1,%2,%3}, {%4,%5,%6,%7}, {%8,%9}, {%0,%1,%2,%3};"                    \
        : "+f"((accp)[0]), "+f"((accp)[1]), "+f"((accp)[2]), "+f"((accp)[3])       \
        : "r"(a0), "r"(a1), "r"(a2), "r"(a3), "r"(b0), "r"(b1))

// ============================ gemm1: X16[M,320] @ W1h[.,320]^T -> PRE16 ============================
// R7-exact config: 128 threads, 2x2 warps, 64x64 warp tiles, 3-stage cp.async, scalar LDS.
__device__ __forceinline__ void g1_load(__half* dst, const __half* __restrict__ X,
                                        const __half* __restrict__ W,
                                        int M, int bm, int ncol, int k0, int tid) {
    const int r0 = tid >> 2;          // 0..31
    const int cq = (tid & 3) * 8;     // half offset: 0,8,16,24 (16B chunks)
#pragma unroll
    for (int i = 0; i < 4; i++) {
        const int row = r0 + i * 32;
        {
            const bool ok = (bm + row) < M;
            const __half* ga = ok ? (X + (size_t)(bm + row) * 320 + k0 + cq) : X;
            uint32_t sa = smem_u32(dst + row * SROW_H + cq);
            uint32_t sz = ok ? 16u : 0u;
            asm volatile("cp.async.cg.shared.global [%0], [%1], 16, %2;"
                         :: "r"(sa), "l"(ga), "r"(sz) : "memory");
        }
        {
            const __half* gb = W + (size_t)(ncol + row) * 320 + k0 + cq;
            uint32_t sb = smem_u32(dst + TILE_H + row * SROW_H + cq);
            asm volatile("cp.async.cg.shared.global [%0], [%1], 16;"
                         :: "r"(sb), "l"(gb) : "memory");
        }
    }
}

__global__ __launch_bounds__(128, 2)
void gemm1_h(const __half* __restrict__ X, const __half* __restrict__ W,
             __half* __restrict__ C, int M, int bn0) {
    extern __shared__ __half smh[];
    const int tid  = threadIdx.x;
    const int wid  = tid >> 5;
    const int lane = tid & 31;
    const int wm = wid & 1, wn = wid >> 1;     // 2x2 warp grid, 64x64 warp tiles
    const int g  = lane >> 2, c4 = lane & 3;
    const int bm = blockIdx.y * 128;           // grid: x = col tiles (fast), y = row tiles
    const int ncol = bn0 + blockIdx.x * 128;
    const int KC = 10;

    float acc[4][8][4];
#pragma unroll
    for (int mt = 0; mt < 4; mt++)
#pragma unroll
        for (int nt = 0; nt < 8; nt++)
#pragma unroll
            for (int i = 0; i < 4; i++) acc[mt][nt][i] = 0.f;

    g1_load(smh, X, W, M, bm, ncol, 0, tid);
    asm volatile("cp.async.commit_group;" ::: "memory");
    g1_load(smh + STAGE_H, X, W, M, bm, ncol, 32, tid);
    asm volatile("cp.async.commit_group;" ::: "memory");
    asm volatile("cp.async.wait_group 1;" ::: "memory");
    __syncthreads();

    int st = 0;
    for (int ci = 0; ci < KC; ci++) {
        const __half* As = smh + (size_t)st * STAGE_H;
        const __half* Bs = As + TILE_H;
#pragma unroll
        for (int ks = 0; ks < 2; ks++) {
            const int kb = ks * 16;
            uint32_t a[4][4];
#pragma unroll
            for (int mt = 0; mt < 4; mt++) {
                const __half* ap = As + (wm * 64 + mt * 16 + g) * SROW_H + kb + 2 * c4;
                a[mt][0] = *(const uint32_t*)ap;
                a[mt][1] = *(const uint32_t*)(ap + 8 * SROW_H);
                a[mt][2] = *(const uint32_t*)(ap + 8);
                a[mt][3] = *(const uint32_t*)(ap + 8 * SROW_H + 8);
            }
            uint32_t b[8][2];
#pragma unroll
            for (int nt = 0; nt < 8; nt++) {
                const __half* bp = Bs + (wn * 64 + nt * 8 + g) * SROW_H + kb + 2 * c4;
                b[nt][0] = *(const uint32_t*)bp;
                b[nt][1] = *(const uint32_t*)(bp + 8);
            }
#pragma unroll
            for (int mt = 0; mt < 4; mt++)
#pragma unroll
                for (int nt = 0; nt < 8; nt++)
                    HMMA(acc[mt][nt], a[mt][0], a[mt][1], a[mt][2], a[mt][3],
                         b[nt][0], b[nt][1]);
        }
        if (ci + 2 < KC) {
            int sn = st + 2; if (sn >= 3) sn -= 3;
            g1_load(smh + (size_t)sn * STAGE_H, X, W, M, bm, ncol, (ci + 2) * 32, tid);
            asm volatile("cp.async.commit_group;" ::: "memory");
            asm volatile("cp.async.wait_group 1;" ::: "memory");
        } else {
            asm volatile("cp.async.wait_group 0;" ::: "memory");
        }
        __syncthreads();
        if (++st == 3) st = 0;
    }

#pragma unroll
    for (int mt = 0; mt < 4; mt++) {
        const int row = bm + wm * 64 + mt * 16 + g;
#pragma unroll
        for (int nt = 0; nt < 8; nt++) {
            const int col = ncol + wn * 64 + nt * 8 + 2 * c4;
            if (row < M)
                *(__half2*)&C[(size_t)row * 1024 + col] =
                    __floats2half2_rn(acc[mt][nt][0], acc[mt][nt][1]);
            if (row + 8 < M)
                *(__half2*)&C[(size_t)(row + 8) * 1024 + col] =
                    __floats2half2_rn(acc[mt][nt][2], acc[mt][nt][3]);
        }
    }
}

// ============================ merged per-level GEMM (fp16, d >= 7) ============================
#define HMMA_COMPUTE(As, Bs)                                                       \
    do {                                                                           \
        _Pragma("unroll")                                                          \
        for (int ks = 0; ks < 2; ks++) {                                           \
            const int kb = ks * 16;                                                \
            uint32_t a[2][4];                                                      \
            _Pragma("unroll")                                                      \
            for (int mt = 0; mt < 2; mt++) {                                       \
                const __half* ap = (As) + (wm * 32 + mt * 16 + g) * SROW_H + kb + 2 * c4; \
                a[mt][0] = *(const uint32_t*)ap;                                   \
                a[mt][1] = *(const uint32_t*)(ap + 8 * SROW_H);                    \
                a[mt][2] = *(const uint32_t*)(ap + 8);                             \
                a[mt][3] = *(const uint32_t*)(ap + 8 * SROW_H + 8);                \
            }                                                                      \
            uint32_t b[8][2];                                                      \
            _Pragma("unroll")                                                      \
            for (int nt = 0; nt < 8; nt++) {                                       \
                const __half* bp = (Bs) + (wn * 64 + nt * 8 + g) * SROW_H + kb + 2 * c4; \
                b[nt][0] = *(const uint32_t*)bp;                                   \
                b[nt][1] = *(const uint32_t*)(bp + 8);                             \
            }                                                                      \
            _Pragma("unroll")                                                      \
            for (int mt = 0; mt < 2; mt++)                                         \
                _Pragma("unroll")                                                  \
                for (int nt = 0; nt < 8; nt++)                                     \
                    HMMA(acc[mt][nt], a[mt][0], a[mt][1], a[mt][2], a[mt][3],      \
                         b[nt][0], b[nt][1]);                                      \
        }                                                                          \
    } while (0)

__global__ __launch_bounds__(256, 2)
void level_gemm_h(int S, int sc, int tiles_m_iou) {
    extern __shared__ __half smh[];

    const int tid  = threadIdx.x;
    const int wid  = tid >> 5;
    const int lane = tid & 31;
    const int wm = wid & 3, wn = wid >> 2;
    const int g  = lane >> 2, c4 = lane & 3;

    int t = blockIdx.x;
    const bool is_iou = (t < tiles_m_iou * 6);
    int tm, tn, ldc;
    const __half* Bsrc;
    __half* C;
    if (is_iou) { tm = t / 6; tn = t - tm * 6; Bsrc = g_WIOUh + (size_t)tn * 128 * 256; C = g_PIOU16; ldc = 768; }
    else { int t2 = t - tiles_m_iou * 6; tm = t2 >> 1; tn = t2 & 1; Bsrc = g_WFh + (size_t)tn * 128 * 256; C = g_PF16; ldc = 256; }
    const int bm = tm * 128;

    const int r  = tid >> 1;           // 0..127 (A/B staging row)
    const int hq = (tid & 1) * 16;     // half offset 0 or 16

    float acc[2][8][4];
#pragma unroll
    for (int mt = 0; mt < 2; mt++)
#pragma unroll
        for (int nt = 0; nt < 8; nt++)
#pragma unroll
            for (int i = 0; i < 4; i++) acc[mt][nt][i] = 0.f;

    uint4 ua0, ua1;

#define LGH_LOAD_A(ci)                                                                    \
    do {                                                                                  \
        const int k0 = (ci) * 32;                                                         \
        if (is_iou) {                                                                     \
            const __half* pl = g_H16 + (size_t)(sc + 2 * (bm + r)) * 256 + k0 + hq;       \
            const __half* pr = pl + 256;                                                  \
            uint4 l0 = *(const uint4*)pl, l1 = *(const uint4*)(pl + 8);                   \
            uint4 r0_ = *(const uint4*)pr, r1_ = *(const uint4*)(pr + 8);                 \
            ua0.x = hadd2u(l0.x, r0_.x); ua0.y = hadd2u(l0.y, r0_.y);                     \
            ua0.z = hadd2u(l0.z, r0_.z); ua0.w = hadd2u(l0.w, r0_.w);                     \
            ua1.x = hadd2u(l1.x, r1_.x); ua1.y = hadd2u(l1.y, r1_.y);                     \
            ua1.z = hadd2u(l1.z, r1_.z); ua1.w = hadd2u(l1.w, r1_.w);                     \
        } else {                                                                          \
            const __half* p = g_H16 + (size_t)(sc + bm + r) * 256 + k0 + hq;              \
            ua0 = *(const uint4*)p; ua1 = *(const uint4*)(p + 8);                         \
        }                                                                                 \
    } while (0)

#define LGH_STORE_A(As)                                                                   \
    do {                                                                                  \
        *(uint4*)&(As)[r * SROW_H + hq]     = ua0;                                        \
        *(uint4*)&(As)[r * SROW_H + hq + 8] = ua1;                                        \
    } while (0)

#define LGH_CPASYNC_B(ci, Bs)                                                             \
    do {                                                                                  \
        const int k0 = (ci) * 32;                                                         \
        const __half* gb = Bsrc + (size_t)r * 256 + k0 + hq;                              \
        uint32_t sb = smem_u32(&(Bs)[r * SROW_H + hq]);                                   \
        asm volatile("cp.async.cg.shared.global [%0], [%1], 16;" :: "r"(sb), "l"(gb) : "memory"); \
        asm volatile("cp.async.cg.shared.global [%0], [%1], 16;" :: "r"(sb + 16u), "l"(gb + 8) : "memory"); \
    } while (0)

    // prologue: chunk 0
    LGH_LOAD_A(0);
    LGH_CPASYNC_B(0, smh + TILE_H);
    asm volatile("cp.async.commit_group;" ::: "memory");
    LGH_STORE_A(smh);
    asm volatile("cp.async.wait_group 0;" ::: "memory");
    __syncthreads();

    for (int ci = 0; ci < 8; ci++) {
        __half* bufn = smh + (size_t)((ci + 1) & 1) * STAGE_H;
        if (ci + 1 < 8) {
            LGH_LOAD_A(ci + 1);
            LGH_CPASYNC_B(ci + 1, bufn + TILE_H);
            asm volatile("cp.async.commit_group;" ::: "memory");
        }
        const __half* As = smh + (size_t)(ci & 1) * STAGE_H;
        const __half* Bs = As + TILE_H;
        HMMA_COMPUTE(As, Bs);
        __syncthreads();
        if (ci + 1 < 8) {
            LGH_STORE_A(bufn);
            asm volatile("cp.async.wait_group 0;" ::: "memory");
            __syncthreads();
        }
    }

#pragma unroll
    for (int mt = 0; mt < 2; mt++) {
        const int row = bm + wm * 32 + mt * 16 + g;
#pragma unroll
        for (int nt = 0; nt < 8; nt++) {
            const int col = tn * 128 + wn * 64 + nt * 8 + 2 * c4;
            *(__half2*)&C[(size_t)row * ldc + col] =
                __floats2half2_rn(acc[mt][nt][0], acc[mt][nt][1]);
            *(__half2*)&C[(size_t)(row + 8) * ldc + col] =
                __floats2half2_rn(acc[mt][nt][2], acc[mt][nt][3]);
        }
    }
#undef LGH_LOAD_A
#undef LGH_STORE_A
#undef LGH_CPASYNC_B
}

// ============================ epilogues ============================
__device__ __forceinline__ float sigmoidf_(float x) { return __fdividef(1.f, 1.f + __expf(-x)); }
__device__ __forceinline__ float ftanh_(float x) {
    float t = __expf(2.f * x);
    return 1.f - __fdividef(2.f, t + 1.f);
}
__device__ __forceinline__ float4 f4add(float4 a, float4 b) {
    return make_float4(a.x + b.x, a.y + b.y, a.z + b.z, a.w + b.w);
}
__device__ __forceinline__ void store_h16(int n, int q, float4 hn) {
    __half2 lo = __floats2half2_rn(hn.x, hn.y);
    __half2 hi = __floats2half2_rn(hn.z, hn.w);
    uint2 v = make_uint2(*reinterpret_cast<uint32_t*>(&lo), *reinterpret_cast<uint32_t*>(&hi));
    *(uint2*)&g_H16[(size_t)n * 256 + q] = v;
}

__global__ void leaf_epi(float* __restrict__ c, float* __restrict__ h) {
    const int j = threadIdx.x >> 6;
    const int q = (threadIdx.x & 63) * 4;
    const int n = LEAF_START + blockIdx.x * 4 + j;
    const __half* pre = g_PRE16 + (size_t)n * 1024;
    float4 pi = f4add(ld_h4(pre + q),       *(const float4*)&g_BIO[q]);
    float4 po = f4add(ld_h4(pre + 256 + q), *(const float4*)&g_BIO[256 + q]);
    float4 pu = f4add(ld_h4(pre + 512 + q), *(const float4*)&g_BIO[512 + q]);
    float4 cn, hn;
#define GATE(X) do { \
        float iv = sigmoidf_(pi.X), ov = sigmoidf_(po.X), uv = ftanh_(pu.X); \
        float cv = iv * uv; cn.X = cv; hn.X = ov * ftanh_(cv); } while (0)
    GATE(x); GATE(y); GATE(z); GATE(w);
#undef GATE
    *(float4*)&c[(size_t)n * NMEM + q] = cn;
    *(float4*)&h[(size_t)n * NMEM + q] = hn;
    store_h16(n, q, hn);
}

__global__ void level_epi(float* __restrict__ c, float* __restrict__ h,
                          int start, int sc, int S) {
    const int j = threadIdx.x >> 6;
    const int q = (threadIdx.x & 63) * 4;
    const int r = blockIdx.x * 4 + j;
    const int n = start + r;
    const __half* pre  = g_PRE16 + (size_t)n * 1024;
    const __half* piou = g_PIOU16 + (size_t)r * 768;
    float4 pi = f4add(f4add(ld_h4(piou + q),       ld_h4(pre + q)),       *(const float4*)&g_BIO[q]);
    float4 po = f4add(f4add(ld_h4(piou + 256 + q), ld_h4(pre + 256 + q)), *(const float4*)&g_BIO[256 + q]);
    float4 pu = f4add(f4add(ld_h4(piou + 512 + q), ld_h4(pre + 512 + q)), *(const float4*)&g_BIO[512 + q]);
    float4 fx = f4add(ld_h4(pre + 768 + q), *(const float4*)&g_BF[q]);
    float4 pfl = f4add(ld_h4(g_PF16 + (size_t)(2 * r) * 256 + q), fx);
    float4 pfr = f4add(ld_h4(g_PF16 + (size_t)(2 * r + 1) * 256 + q), fx);
    float4 cl = *(const float4*)&c[(size_t)(sc + 2 * r) * NMEM + q];
    float4 cr = *(const float4*)&c[(size_t)(sc + 2 * r + 1) * NMEM + q];
    float4 cn, hn;
#define GATE(X) do { \
        float iv = sigmoidf_(pi.X), ov = sigmoidf_(po.X), uv = ftanh_(pu.X); \
        float fl = sigmoidf_(pfl.X), fr = sigmoidf_(pfr.X); \
        float cv = iv * uv + fl * cl.X + fr * cr.X; \
        cn.X = cv; hn.X = ov * ftanh_(cv); } while (0)
    GATE(x); GATE(y); GATE(z); GATE(w);
#undef GATE
    *(float4*)&c[(size_t)n * NMEM + q] = cn;
    *(float4*)&h[(size_t)n * NMEM + q] = hn;
    store_h16(n, q, hn);
}

// ============================ fused small levels (d <= 6, S <= 64) ============================
__global__ __launch_bounds__(256)
void fused_small(float* __restrict__ c, float* __restrict__ h, int start, int sc) {
    __shared__ float s_hsum[256], s_hl[256], s_hr[256];
    const int r = blockIdx.x, t = threadIdx.x;
    const int n = start + r;
    const int lc = sc + 2 * r;
    float hl = h[(size_t)lc * NMEM + t];
    float hr = h[(size_t)(lc + 1) * NMEM + t];
    s_hl[t] = hl; s_hr[t] = hr; s_hsum[t] = hl + hr;
    __syncthreads();

    const __half* w0 = g_WIOUh + (size_t)t * 256;
    const __half* w1 = w0 + 256 * 256;
    const __half* w2 = w1 + 256 * 256;
    const __half* wf = g_WFh + (size_t)t * 256;

    float di = 0.f, dq = 0.f, du = 0.f, dfl = 0.f, dfr = 0.f;
#pragma unroll 4
    for (int k = 0; k < 256; k += 8) {
        uint4 u0 = *(const uint4*)&w0[k];
        uint4 u1 = *(const uint4*)&w1[k];
        uint4 u2 = *(const uint4*)&w2[k];
        uint4 uf = *(const uint4*)&wf[k];
#pragma unroll
        for (int p = 0; p < 4; p++) {
            uint32_t b0 = (&u0.x)[p], b1 = (&u1.x)[p], b2 = (&u2.x)[p], bf = (&uf.x)[p];
            float2 f0 = __half22float2(*reinterpret_cast<__half2*>(&b0));
            float2 f1 = __half22float2(*reinterpret_cast<__half2*>(&b1));
            float2 f2 = __half22float2(*reinterpret_cast<__half2*>(&b2));
            float2 ff = __half22float2(*reinterpret_cast<__half2*>(&bf));
            float hs0 = s_hsum[k + 2 * p], hs1 = s_hsum[k + 2 * p + 1];
            float l0 = s_hl[k + 2 * p],   l1 = s_hl[k + 2 * p + 1];
            float r0 = s_hr[k + 2 * p],   r1 = s_hr[k + 2 * p + 1];
            di  = fmaf(f0.x, hs0, fmaf(f0.y, hs1, di));
            dq  = fmaf(f1.x, hs0, fmaf(f1.y, hs1, dq));
            du  = fmaf(f2.x, hs0, fmaf(f2.y, hs1, du));
            dfl = fmaf(ff.x, l0,  fmaf(ff.y, l1,  dfl));
            dfr = fmaf(ff.x, r0,  fmaf(ff.y, r1,  dfr));
        }
    }

    const __half* pre = g_PRE16 + (size_t)n * 1024;
    float iv = sigmoidf_(di + __half2float(pre[t])       + g_BIO[t]);
    float ov = sigmoidf_(dq + __half2float(pre[256 + t]) + g_BIO[256 + t]);
    float uv = ftanh_(   du + __half2float(pre[512 + t]) + g_BIO[512 + t]);
    float fx = __half2float(pre[768 + t]) + g_BF[t];
    float fl = sigmoidf_(dfl + fx);
    float fr = sigmoidf_(dfr + fx);
    float cl = c[(size_t)lc * NMEM + t];
    float cr = c[(size_t)(lc + 1) * NMEM + t];
    float cn = iv * uv + fl * cl + fr * cr;
    float hn = ov * ftanh_(cn);
    c[(size_t)n * NMEM + t] = cn;
    h[(size_t)n * NMEM + t] = hn;
    g_H16[(size_t)n * 256 + t] = __float2half_rn(hn);
}

// ============================ launcher ============================
extern "C" void kernel_launch(void* const* d_in, const int* in_sizes, int n_in,
                              void* d_out, int out_size) {
    const float* inputs = (const float*)d_in[0];
    const float* W_ioux = (const float*)d_in[1];
    const float* b_ioux = (const float*)d_in[2];
    const float* W_iouh = (const float*)d_in[3];
    const float* b_iouh = (const float*)d_in[4];
    const float* W_fx   = (const float*)d_in[5];
    const float* b_fx   = (const float*)d_in[6];
    const float* W_fh   = (const float*)d_in[7];
    const float* b_fh   = (const float*)d_in[8];
    (void)in_sizes; (void)n_in; (void)out_size;

    float* c = (float*)d_out;                   // out[0] = c  [N,256]
    float* h = c + (size_t)NN * NMEM;           // out[1] = h  [N,256]

    __half *pPRE16, *pX16, *pW1h;
    cudaGetSymbolAddress((void**)&pPRE16, g_PRE16);
    cudaGetSymbolAddress((void**)&pX16,   g_X16);
    cudaGetSymbolAddress((void**)&pW1h,   g_W1h);

    const int SMEM1 = 3 * STAGE_H * 2;   // 61440 B (3-stage fp16)
    const int SMEML = 2 * STAGE_H * 2;   // 40960 B (2-stage fp16)
    cudaFuncSetAttribute(gemm1_h,      cudaFuncAttributeMaxDynamicSharedMemorySize, SMEM1);
    cudaFuncSetAttribute(level_gemm_h, cudaFuncAttributeMaxDynamicSharedMemorySize, SMEML);

    conv_x<<<(NN * 160 + 255) / 256, 256>>>(inputs);
    build_w1h<<<(1024 * 320 + 255) / 256, 256>>>(W_ioux, W_fx);
    build_misch<<<(263168 + 255) / 256, 256>>>(W_iouh, W_fh, b_ioux, b_iouh, b_fx, b_fh);

    // gemm1a: iou cols (0..767) for ALL nodes  (6 col tiles of 128)
    {
        dim3 grd(6, 512);
        gemm1_h<<<grd, 128, SMEM1>>>(pX16, pW1h, pPRE16, NN, 0);
    }
    // gemm1b: fx cols (768..1023) for INTERNAL nodes only (leaves' fx is dead work)
    {
        dim3 grd(2, 256);
        gemm1_h<<<grd, 128, SMEM1>>>(pX16, pW1h, pPRE16, LEAF_START, 768);
    }

    // leaves (depth 15)
    leaf_epi<<<8192, 256>>>(c, h);

    // big internal levels (S multiple of 128)
    for (int d = 14; d >= 7; --d) {
        const int S = 1 << d;
        const int start = S - 1;
        const int sc = 2 * S - 1;
        const int tiles_m_iou = S / 128;
        const int gx = tiles_m_iou * 6 + (2 * S / 128) * 2;
        level_gemm_h<<<gx, 256, SMEML>>>(S, sc, tiles_m_iou);
        level_epi<<<S / 4, 256>>>(c, h, start, sc, S);
    }

    // small levels (d <= 6): fused GEMM + epilogue, one launch per level
    for (int d = 6; d >= 0; --d) {
        const int S = 1 << d;
        fused_small<<<S, 256>>>(c, h, S - 1, 2 * S - 1);
    }
}